// round 1
// baseline (speedup 1.0000x reference)
#include <cuda_runtime.h>

// Problem dims (fixed by the dataset)
#define NCLS 19
#define HW_  (512*1024)          // 2^19
#define NPIX (4*HW_)             // 2,097,152

// ---- scratch (static __device__ — no allocations allowed) ----
__device__ float    g_loss[NPIX];        // 8 MB
__device__ unsigned g_hist0[4096];
__device__ unsigned g_hist1[4096];
__device__ unsigned g_hist2[256];
__device__ unsigned g_prefix0, g_prefix01, g_k1, g_k2;
__device__ float    g_thresh;
__device__ double   g_sum;
__device__ unsigned g_cnt;
__device__ int      g_tmode;             // 1 = targets are int64, 0 = int32

// ------------------------------------------------------------------
__global__ void k_init(const void* tgt_raw) {
    int t = blockIdx.x * blockDim.x + threadIdx.x;
    if (t < 4096) { g_hist0[t] = 0; g_hist1[t] = 0; }
    if (t < 256)  g_hist2[t] = 0;
    if (t == 0) {
        g_prefix0  = 0xFFFFFFFFu;
        g_prefix01 = 0xFFFFFFFFu;
        g_k1 = 0; g_k2 = 0;
        g_thresh = __int_as_float(0xFF800000);   // -inf (fallback: keep all)
        g_sum = 0.0; g_cnt = 0;
        // dtype detection: if buffer is int32 (values 0..18) reinterpreted as
        // int64, the high word is the next class index -> almost surely >= 2^32.
        const long long* t64 = (const long long*)tgt_raw;
        int is64 = 1;
        #pragma unroll
        for (int i = 0; i < 8; i++) {
            long long v = t64[i];
            if (v < 0 || v >= (long long)NCLS) is64 = 0;
        }
        g_tmode = is64;
    }
}

// ------------------------------------------------------------------
// Pass A: fused log_softmax NLL + level-0 bit histogram (bits[31:20])
__global__ void k_loss(const float* __restrict__ logits, const void* __restrict__ tgt_raw) {
    __shared__ unsigned sh[4096];
    for (int i = threadIdx.x; i < 4096; i += blockDim.x) sh[i] = 0;
    __syncthreads();

    const int tmode = g_tmode;
    const long long* t64 = (const long long*)tgt_raw;
    const int*       t32 = (const int*)tgt_raw;

    int stride = gridDim.x * blockDim.x;
    for (int p = blockIdx.x * blockDim.x + threadIdx.x; p < NPIX; p += stride) {
        int n  = p >> 19;
        int hw = p & (HW_ - 1);
        const float* base = logits + (size_t)n * (size_t)(NCLS * (size_t)HW_) + hw;
        int t = tmode ? (int)t64[p] : t32[p];

        float v[NCLS];
        float mx = -3.4e38f, xt = 0.f;
        #pragma unroll
        for (int c = 0; c < NCLS; c++) {
            float x = __ldg(base + (size_t)c * HW_);
            v[c] = x;
            mx = fmaxf(mx, x);
            if (c == t) xt = x;       // select chain, no dynamic indexing
        }
        float s = 0.f;
        #pragma unroll
        for (int c = 0; c < NCLS; c++) s += __expf(v[c] - mx);

        float loss = __logf(s) + (mx - xt);
        g_loss[p] = loss;
        if (loss > 0.f)
            atomicAdd(&sh[__float_as_uint(loss) >> 20], 1u);
    }
    __syncthreads();
    for (int i = threadIdx.x; i < 4096; i += blockDim.x) {
        unsigned c = sh[i];
        if (c) atomicAdd(&g_hist0[i], c);
    }
}

// ------------------------------------------------------------------
// Scan a 4096-bin histogram from the top to locate the bin containing the
// k-th largest element. level 0: k derived from n_valid; level 1: k = g_k1.
__global__ void k_scan(int level) {
    __shared__ unsigned cnts_s[4096];
    __shared__ unsigned scan_s[1024];
    const unsigned* hist = (level == 0) ? g_hist0 : g_hist1;
    int t = threadIdx.x;          // 1024 threads

    unsigned csum = 0;
    #pragma unroll
    for (int i = 0; i < 4; i++) {
        int j = t * 4 + i;                    // descending-order index
        unsigned v = hist[4095 - j];
        cnts_s[j] = v;
        csum += v;
    }
    scan_s[t] = csum;
    __syncthreads();
    for (int off = 1; off < 1024; off <<= 1) {
        unsigned add = (t >= off) ? scan_s[t - off] : 0u;
        __syncthreads();
        scan_s[t] += add;
        __syncthreads();
    }
    unsigned total = scan_s[1023];

    unsigned k;
    if (level == 0) {
        if (total == 0) {                      // no valid pixels: mean of all
            if (t == 0) { g_prefix0 = 0xFFFFFFFFu; g_prefix01 = 0xFFFFFFFFu; }
            return;
        }
        unsigned nk = (unsigned)(0.7f * (float)total);   // matches ref fp32 trunc
        if (nk < 100000u) nk = 100000u;
        if (nk > total)   nk = total;
        k = nk;
    } else {
        if (g_prefix0 == 0xFFFFFFFFu) {
            if (t == 0) g_prefix01 = 0xFFFFFFFFu;
            return;
        }
        k = g_k1;
    }

    unsigned hi = scan_s[t];
    unsigned lo = hi - csum;
    if (k > lo && k <= hi) {                  // exactly one thread wins
        unsigned cum = lo;
        #pragma unroll
        for (int i = 0; i < 4; i++) {
            unsigned v = cnts_s[t * 4 + i];
            cum += v;
            if (k <= cum) {
                unsigned bin = 4095 - (unsigned)(t * 4 + i);
                unsigned r   = k - (cum - v);
                if (level == 0) { g_prefix0 = bin; g_k1 = r; }
                else            { g_prefix01 = (g_prefix0 << 12) | bin; g_k2 = r; }
                break;
            }
        }
    }
}

// ------------------------------------------------------------------
// Level-1 histogram: bits[19:8] of losses whose bits[31:20] match prefix0
__global__ void k_hist1() {
    __shared__ unsigned sh[4096];
    for (int i = threadIdx.x; i < 4096; i += blockDim.x) sh[i] = 0;
    __syncthreads();
    unsigned pref = g_prefix0;
    int stride = gridDim.x * blockDim.x;
    for (int p = blockIdx.x * blockDim.x + threadIdx.x; p < NPIX; p += stride) {
        float l = g_loss[p];
        if (l > 0.f) {
            unsigned b = __float_as_uint(l);
            if ((b >> 20) == pref) atomicAdd(&sh[(b >> 8) & 0xFFFu], 1u);
        }
    }
    __syncthreads();
    for (int i = threadIdx.x; i < 4096; i += blockDim.x) {
        unsigned c = sh[i];
        if (c) atomicAdd(&g_hist1[i], c);
    }
}

// ------------------------------------------------------------------
// Level-2 histogram: low 8 bits within the selected 24-bit prefix (few hits)
__global__ void k_hist2() {
    unsigned pref = g_prefix01;
    int stride = gridDim.x * blockDim.x;
    for (int p = blockIdx.x * blockDim.x + threadIdx.x; p < NPIX; p += stride) {
        float l = g_loss[p];
        if (l > 0.f) {
            unsigned b = __float_as_uint(l);
            if ((b >> 8) == pref) atomicAdd(&g_hist2[b & 0xFFu], 1u);
        }
    }
}

__global__ void k_scan2() {
    __shared__ unsigned sh[256];
    int t = threadIdx.x;
    sh[t] = g_hist2[t];
    __syncthreads();
    if (t == 0) {
        unsigned pref = g_prefix01;
        if (pref != 0xFFFFFFFFu) {
            unsigned k = g_k2, cum = 0;
            for (int b = 255; b >= 0; b--) {
                cum += sh[b];
                if (cum >= k) {
                    g_thresh = __uint_as_float((pref << 8) | (unsigned)b);
                    break;
                }
            }
        }
    }
}

// ------------------------------------------------------------------
// Final masked reduction: sum & count of loss >= thresh
__global__ void k_reduce() {
    __shared__ double   ssum[256];
    __shared__ unsigned scnt[256];
    float th = g_thresh;
    double s = 0.0; unsigned c = 0;
    int stride = gridDim.x * blockDim.x;
    for (int p = blockIdx.x * blockDim.x + threadIdx.x; p < NPIX; p += stride) {
        float l = g_loss[p];
        if (l >= th) { s += (double)l; c++; }
    }
    ssum[threadIdx.x] = s; scnt[threadIdx.x] = c;
    __syncthreads();
    for (int off = 128; off > 0; off >>= 1) {
        if (threadIdx.x < off) {
            ssum[threadIdx.x] += ssum[threadIdx.x + off];
            scnt[threadIdx.x] += scnt[threadIdx.x + off];
        }
        __syncthreads();
    }
    if (threadIdx.x == 0) {
        atomicAdd(&g_sum, ssum[0]);
        atomicAdd(&g_cnt, scnt[0]);
    }
}

__global__ void k_final(float* out) {
    unsigned c = g_cnt;
    if (c == 0) c = 1;
    out[0] = (float)(g_sum / (double)c);
}

// ------------------------------------------------------------------
extern "C" void kernel_launch(void* const* d_in, const int* in_sizes, int n_in,
                              void* d_out, int out_size) {
    const float* logits = (const float*)d_in[0];
    const void*  tgt    = d_in[1];
    float* out = (float*)d_out;

    const int GRID = 1184;   // 8 CTAs/SM on 148 SMs
    const int TB   = 256;

    k_init  <<<16, 256>>>(tgt);
    k_loss  <<<GRID, TB>>>(logits, tgt);
    k_scan  <<<1, 1024>>>(0);
    k_hist1 <<<GRID, TB>>>();
    k_scan  <<<1, 1024>>>(1);
    k_hist2 <<<GRID, TB>>>();
    k_scan2 <<<1, 256>>>();
    k_reduce<<<GRID, TB>>>();
    k_final <<<1, 1>>>(out);
}